// round 12
// baseline (speedup 1.0000x reference)
#include <cuda_runtime.h>
#include <cuda_fp16.h>
#include <math.h>

#define N_NODES 100000
#define E_IN    1600000
#define E_TOT   (E_IN + N_NODES)
#define F_IN    256
#define H1      8
#define C1      64      /* H1*F1 */
#define C2      40      /* classes */

#define G1_BLOCKS ((N_NODES + 127) / 128)          /* 782 gemm1 tiles   */
#define HB_BLOCKS ((E_TOT + 255) / 256)            /* 6641 hist chunks  */
#define SC_BLOCKS ((N_NODES + 255) / 256)          /* 391 scan blocks   */

// ---------------- scratch (static device globals; no allocation) ----------------
__device__ uint4 g_h1p[(size_t)N_NODES * 8];   // layer-1 features, fp16: 8 halves per uint4
__device__ uint4 g_h2p[(size_t)N_NODES * 5];   // layer-2 features, fp16: 40 halves = 5 uint4
__device__ float g_as1[(size_t)N_NODES * H1];
__device__ float g_ad1[(size_t)N_NODES * H1];
__device__ float g_x2 [(size_t)N_NODES * C1];
__device__ float g_as2[N_NODES];
__device__ float g_ad2[N_NODES];
__device__ float g_w1 [(size_t)E_TOT * H1];    // per-edge per-head layer-1 weights (CSR order)
__device__ float g_w2 [E_TOT];                 // per-edge layer-2 weights (CSR order)
__device__ int   g_dst[E_TOT];                 // dst node per CSR slot
__device__ int   g_deg[N_NODES];
__device__ int   g_cur[N_NODES];
__device__ int   g_off[N_NODES + 1];
__device__ int   g_csr[E_TOT];
__device__ int   g_part[SC_BLOCKS];
__device__ int   g_poff[SC_BLOCKS];

// ---------------- helpers ----------------
__device__ __forceinline__ float tf32r(float v) {
    unsigned u;
    asm("cvt.rna.tf32.f32 %0, %1;" : "=r"(u) : "f"(v));
    return __uint_as_float(u);
}
__device__ __forceinline__ void mma_tf32(float* c, const unsigned* a, const unsigned* b) {
    asm volatile(
        "mma.sync.aligned.m16n8k8.row.col.f32.tf32.tf32.f32 "
        "{%0,%1,%2,%3}, {%4,%5,%6,%7}, {%8,%9}, {%0,%1,%2,%3};\n"
        : "+f"(c[0]), "+f"(c[1]), "+f"(c[2]), "+f"(c[3])
        : "r"(a[0]), "r"(a[1]), "r"(a[2]), "r"(a[3]), "r"(b[0]), "r"(b[1]));
}
__device__ __forceinline__ unsigned long long packf2(float a, float b) {
    unsigned long long r;
    asm("mov.b64 %0, {%1, %2};" : "=l"(r) : "f"(a), "f"(b));
    return r;
}
__device__ __forceinline__ void fma2(unsigned long long& d,
                                     unsigned long long a, unsigned long long b) {
    asm("fma.rn.f32x2 %0, %1, %2, %0;" : "+l"(d) : "l"(a), "l"(b));
}
__device__ __forceinline__ float2 unpk(unsigned long long v) {
    float2 r;
    asm("mov.b64 {%0, %1}, %2;" : "=f"(r.x), "=f"(r.y) : "l"(v));
    return r;
}
__device__ __forceinline__ float lrelu(float v) { return v > 0.f ? v : 0.2f * v; }

// ---------------- CSR build ----------------
__global__ void zero_kernel() {
    int i = blockIdx.x * blockDim.x + threadIdx.x;
    if (i < N_NODES) { g_deg[i] = 0; g_cur[i] = 0; }
}

__global__ void scanA_kernel() {
    __shared__ int ws[8];
    int tid = threadIdx.x;
    int i = blockIdx.x * 256 + tid;
    int v = (i < N_NODES) ? g_deg[i] : 0;
    int s = v;
#pragma unroll
    for (int o = 16; o > 0; o >>= 1) s += __shfl_xor_sync(0xffffffffu, s, o);
    if ((tid & 31) == 0) ws[tid >> 5] = s;
    __syncthreads();
    if (tid < 8) {
        int t = ws[tid];
#pragma unroll
        for (int o = 4; o > 0; o >>= 1) t += __shfl_xor_sync(0xffu, t, o);
        if (tid == 0) g_part[blockIdx.x] = t;
    }
}

__global__ void scanB_kernel() {
    __shared__ int sh[512];
    int t = threadIdx.x;
    int v = (t < SC_BLOCKS) ? g_part[t] : 0;
    sh[t] = v;
    __syncthreads();
    for (int o = 1; o < 512; o <<= 1) {
        int u = (t >= o) ? sh[t - o] : 0;
        __syncthreads();
        sh[t] += u;
        __syncthreads();
    }
    if (t < SC_BLOCKS) g_poff[t] = sh[t] - v;    // exclusive
}

__global__ void scanC_kernel() {
    __shared__ int ws[8];
    int tid = threadIdx.x;
    int i = blockIdx.x * 256 + tid;
    int v = (i < N_NODES) ? g_deg[i] : 0;
    int inc = v;
#pragma unroll
    for (int o = 1; o < 32; o <<= 1) {
        int u = __shfl_up_sync(0xffffffffu, inc, o);
        if ((tid & 31) >= o) inc += u;
    }
    if ((tid & 31) == 31) ws[tid >> 5] = inc;
    __syncthreads();
    if (tid < 8) {
        int t = ws[tid];
#pragma unroll
        for (int o = 1; o < 8; o <<= 1) {
            int u = __shfl_up_sync(0xffu, t, o);
            if (tid >= o) t += u;
        }
        ws[tid] = t;
    }
    __syncthreads();
    int wbase = (tid >= 32) ? ws[(tid >> 5) - 1] : 0;
    int excl = g_poff[blockIdx.x] + wbase + inc - v;
    if (i < N_NODES) {
        g_off[i] = excl;
        if (i == N_NODES - 1) g_off[N_NODES] = excl + v;  // == E_TOT
    }
}

// scatter + layer-1 edge-weight precompute (absorbed in atomic latency slack)
__global__ void scatter_kernel(const int* __restrict__ ei) {
    int i = blockIdx.x * blockDim.x + threadIdx.x;
    if (i >= E_TOT) return;
    int d, s;
    if (i < E_IN) { s = ei[i]; d = ei[E_IN + i]; }
    else          { s = i - E_IN; d = i - E_IN; }
    int p = g_off[d] + atomicAdd(&g_cur[d], 1);
    g_csr[p] = s;
    g_dst[p] = d;
    float4 a0 = *(const float4*)&g_as1[s * H1];
    float4 a1 = *(const float4*)&g_as1[s * H1 + 4];
    float4 b0 = *(const float4*)&g_ad1[d * H1];
    float4 b1 = *(const float4*)&g_ad1[d * H1 + 4];
    float4 w0, w1;
    w0.x = __expf(lrelu(a0.x + b0.x)); w0.y = __expf(lrelu(a0.y + b0.y));
    w0.z = __expf(lrelu(a0.z + b0.z)); w0.w = __expf(lrelu(a0.w + b0.w));
    w1.x = __expf(lrelu(a1.x + b1.x)); w1.y = __expf(lrelu(a1.y + b1.y));
    w1.z = __expf(lrelu(a1.z + b1.z)); w1.w = __expf(lrelu(a1.w + b1.w));
    *(float4*)&g_w1[(size_t)p * H1]     = w0;
    *(float4*)&g_w1[(size_t)p * H1 + 4] = w1;
}

// ---------------- fat kernel: gemm1 (tf32 mma.sync) || hist ----------------
__global__ void __launch_bounds__(256) fat1_kernel(
        const float* __restrict__ x, const float* __restrict__ W1,
        const float* __restrict__ a_s, const float* __restrict__ a_d,
        const int* __restrict__ ei) {
    __shared__ __align__(16) float smem_pool[128 * 65];
    int tid = threadIdx.x;

    if (blockIdx.x >= G1_BLOCKS) {
        int i = (blockIdx.x - G1_BLOCKS) * 256 + tid;
        if (i < E_TOT) {
            int d = (i < E_IN) ? ei[E_IN + i] : (i - E_IN);
            atomicAdd(&g_deg[d], 1);
        }
        return;
    }

    float (*Xs)[33] = (float (*)[33])smem_pool;
    float (*Ws)[64] = (float (*)[64])(smem_pool + 128 * 33);
    float (*Cs)[65] = (float (*)[65])smem_pool;

    int lane = tid & 31;
    int warp = tid >> 5;
    int rg = warp >> 1;
    int cg = warp & 1;
    int row0 = blockIdx.x * 128;

    float acc[2][4][4];
#pragma unroll
    for (int m = 0; m < 2; m++)
#pragma unroll
        for (int j = 0; j < 4; j++)
#pragma unroll
            for (int q = 0; q < 4; q++) acc[m][j][q] = 0.f;

    float4 xbuf[4];
    float4 wbuf[2];
#pragma unroll
    for (int i = 0; i < 4; i++) {
        int idx = tid + i * 256; int r = idx >> 3, q = idx & 7;
        int gr = row0 + r;
        xbuf[i] = (gr < N_NODES) ? *(const float4*)&x[(size_t)gr * F_IN + q * 4]
                                 : make_float4(0.f, 0.f, 0.f, 0.f);
    }
#pragma unroll
    for (int i = 0; i < 2; i++) {
        int idx = tid + i * 256; int r = idx >> 4, q = idx & 15;
        wbuf[i] = *(const float4*)&W1[(size_t)r * C1 + q * 4];
    }

    for (int kt = 0; kt < F_IN; kt += 32) {
#pragma unroll
        for (int i = 0; i < 4; i++) {
            int idx = tid + i * 256; int r = idx >> 3, q = idx & 7;
            Xs[r][q * 4 + 0] = tf32r(xbuf[i].x); Xs[r][q * 4 + 1] = tf32r(xbuf[i].y);
            Xs[r][q * 4 + 2] = tf32r(xbuf[i].z); Xs[r][q * 4 + 3] = tf32r(xbuf[i].w);
        }
#pragma unroll
        for (int i = 0; i < 2; i++) {
            int idx = tid + i * 256; int r = idx >> 4, q = idx & 15;
            Ws[r][q * 4 + 0] = tf32r(wbuf[i].x); Ws[r][q * 4 + 1] = tf32r(wbuf[i].y);
            Ws[r][q * 4 + 2] = tf32r(wbuf[i].z); Ws[r][q * 4 + 3] = tf32r(wbuf[i].w);
        }
        __syncthreads();

        int ktn = kt + 32;
        if (ktn < F_IN) {
#pragma unroll
            for (int i = 0; i < 4; i++) {
                int idx = tid + i * 256; int r = idx >> 3, q = idx & 7;
                int gr = row0 + r;
                xbuf[i] = (gr < N_NODES) ? *(const float4*)&x[(size_t)gr * F_IN + ktn + q * 4]
                                         : make_float4(0.f, 0.f, 0.f, 0.f);
            }
#pragma unroll
            for (int i = 0; i < 2; i++) {
                int idx = tid + i * 256; int r = idx >> 4, q = idx & 15;
                wbuf[i] = *(const float4*)&W1[(size_t)(ktn + r) * C1 + q * 4];
            }
        }

#pragma unroll
        for (int ks = 0; ks < 4; ks++) {
            int k0 = ks * 8;
            unsigned afr[2][4];
#pragma unroll
            for (int m = 0; m < 2; m++) {
                int R = rg * 32 + m * 16;
                afr[m][0] = __float_as_uint(Xs[R + (lane >> 2)][k0 + (lane & 3)]);
                afr[m][1] = __float_as_uint(Xs[R + (lane >> 2) + 8][k0 + (lane & 3)]);
                afr[m][2] = __float_as_uint(Xs[R + (lane >> 2)][k0 + (lane & 3) + 4]);
                afr[m][3] = __float_as_uint(Xs[R + (lane >> 2) + 8][k0 + (lane & 3) + 4]);
            }
            unsigned bfr[4][2];
#pragma unroll
            for (int j = 0; j < 4; j++) {
                int Cb = cg * 32 + j * 8;
                bfr[j][0] = __float_as_uint(Ws[k0 + (lane & 3)][Cb + (lane >> 2)]);
                bfr[j][1] = __float_as_uint(Ws[k0 + (lane & 3) + 4][Cb + (lane >> 2)]);
            }
#pragma unroll
            for (int m = 0; m < 2; m++)
#pragma unroll
                for (int j = 0; j < 4; j++)
                    mma_tf32(acc[m][j], afr[m], bfr[j]);
        }
        __syncthreads();
    }

#pragma unroll
    for (int m = 0; m < 2; m++) {
        int R = rg * 32 + m * 16 + (lane >> 2);
#pragma unroll
        for (int j = 0; j < 4; j++) {
            int Cb = cg * 32 + j * 8 + 2 * (lane & 3);
            Cs[R][Cb]         = acc[m][j][0];
            Cs[R][Cb + 1]     = acc[m][j][1];
            Cs[R + 8][Cb]     = acc[m][j][2];
            Cs[R + 8][Cb + 1] = acc[m][j][3];
        }
    }
    __syncthreads();

    {
        int r = tid >> 1;
        int half = tid & 1;
        int gr = row0 + r;
        if (gr < N_NODES) {
            int c0 = half * 32;
            float f[32];
#pragma unroll
            for (int q = 0; q < 32; q++) f[q] = Cs[r][c0 + q];
#pragma unroll
            for (int h = 0; h < 4; h++) {
                int head = half * 4 + h;
                float ps = 0.f, pd = 0.f;
#pragma unroll
                for (int q = 0; q < 8; q++) {
                    ps += f[h * 8 + q] * a_s[head * 8 + q];
                    pd += f[h * 8 + q] * a_d[head * 8 + q];
                }
                g_as1[gr * H1 + head] = ps;
                g_ad1[gr * H1 + head] = pd;
            }
#pragma unroll
            for (int u = 0; u < 4; u++) {
                __half2 hh[4];
#pragma unroll
                for (int q = 0; q < 4; q++)
                    hh[q] = __floats2half2_rn(f[u * 8 + 2 * q], f[u * 8 + 2 * q + 1]);
                g_h1p[(size_t)gr * 8 + half * 4 + u] = *(uint4*)hh;
            }
        }
    }
}

// ---------------- Aggregation layer 1 (precomputed weights; 4 edges/iter) ----------------
// Lane owns half2 #lane -> head hA = lane>>2. Weight row: g_w1[e*8+lane] covers
// 4 edges x 8 heads in one coalesced 128B load; lane's value = (slot lane>>3, head lane&7).
__global__ void __launch_bounds__(256) agg1_kernel(const float* __restrict__ bias1) {
    int gw = (blockIdx.x * blockDim.x + threadIdx.x) >> 5;
    int lane = threadIdx.x & 31;
    if (gw >= N_NODES) return;
    int n = gw;
    int start = g_off[n], end = g_off[n + 1];
    int hA = lane >> 2;

    float accLo = 0.f, accHi = 0.f, denom = 0.f;
    int e = start;
    int s[4];
#pragma unroll
    for (int j = 0; j < 4; j++) s[j] = (e + j < end) ? g_csr[e + j] : 0;

    while (e + 3 < end) {
        int ns[4];
#pragma unroll
        for (int j = 0; j < 4; j++) ns[j] = (e + 4 + j < end) ? g_csr[e + 4 + j] : 0;
        float w = g_w1[(size_t)e * H1 + lane];      // coalesced: 4 edges x 8 heads
        denom += w;
#pragma unroll
        for (int j = 0; j < 4; j++) {
            float wj = __shfl_sync(0xffffffffu, w, j * 8 + hA);
            __half2 h = ((const __half2*)&g_h1p[(size_t)s[j] * 8])[lane];
            float2 f = __half22float2(h);
            accLo += wj * f.x;
            accHi += wj * f.y;
        }
#pragma unroll
        for (int j = 0; j < 4; j++) s[j] = ns[j];
        e += 4;
    }
    int rem = end - e;           // 0..3, uniform per warp
    if (rem > 0) {
        float w = (lane < rem * 8) ? g_w1[(size_t)e * H1 + lane] : 0.f;
        denom += w;
        for (int j = 0; j < rem; j++) {
            float wj = __shfl_sync(0xffffffffu, w, j * 8 + hA);
            __half2 h = ((const __half2*)&g_h1p[(size_t)s[j] * 8])[lane];
            float2 f = __half22float2(h);
            accLo += wj * f.x;
            accHi += wj * f.y;
        }
    }

    denom += __shfl_xor_sync(0xffffffffu, denom, 8);
    denom += __shfl_xor_sync(0xffffffffu, denom, 16);
    float dA = __shfl_sync(0xffffffffu, denom, hA) + 1e-16f;
    float oLo = accLo / dA + bias1[2 * lane];
    float oHi = accHi / dA + bias1[2 * lane + 1];
    oLo = oLo > 0.f ? oLo : expm1f(oLo);
    oHi = oHi > 0.f ? oHi : expm1f(oHi);
    *(float2*)&g_x2[(size_t)n * C1 + 2 * lane] = make_float2(oLo, oHi);
}

// ---------------- GEMM2: thread-per-node, fp16 packed output ----------------
__global__ void __launch_bounds__(128) gemm2_kernel(
        const float* __restrict__ W2,
        const float* __restrict__ a_s2, const float* __restrict__ a_d2) {
    __shared__ float Ws[C1][C2];
    __shared__ float Xs[128][65];
    int tid = threadIdx.x;
    int n0 = blockIdx.x * 128;
    int gn = n0 + tid;

    for (int i = tid; i < C1 * C2; i += 128) ((float*)Ws)[i] = W2[i];
#pragma unroll
    for (int i = 0; i < 16; i++) {
        int idx = tid + i * 128; int r = idx >> 4, q = idx & 15;
        int gr = n0 + r;
        float4 v = (gr < N_NODES) ? *(const float4*)&g_x2[(size_t)gr * C1 + q * 4]
                                  : make_float4(0.f, 0.f, 0.f, 0.f);
        Xs[r][q * 4 + 0] = v.x; Xs[r][q * 4 + 1] = v.y;
        Xs[r][q * 4 + 2] = v.z; Xs[r][q * 4 + 3] = v.w;
    }
    __syncthreads();

    unsigned long long acc2[20];
#pragma unroll
    for (int j = 0; j < 20; j++) acc2[j] = 0ull;

    if (gn < N_NODES) {
#pragma unroll 4
        for (int k = 0; k < C1; k++) {
            float a = Xs[tid][k];
            unsigned long long ap = packf2(a, a);
            const unsigned long long* wp = (const unsigned long long*)&Ws[k][0];
#pragma unroll
            for (int j = 0; j < 20; j++) fma2(acc2[j], ap, wp[j]);
        }
        float ps = 0.f, pd = 0.f;
        __half2 hh[20];
#pragma unroll
        for (int j = 0; j < 20; j++) {
            float2 p = unpk(acc2[j]);
            hh[j] = __floats2half2_rn(p.x, p.y);
            ps += p.x * a_s2[2 * j] + p.y * a_s2[2 * j + 1];
            pd += p.x * a_d2[2 * j] + p.y * a_d2[2 * j + 1];
        }
        const uint4* hv = (const uint4*)hh;
#pragma unroll
        for (int u = 0; u < 5; u++) g_h2p[(size_t)gn * 5 + u] = hv[u];
        g_as2[gn] = ps;
        g_ad2[gn] = pd;
    }
}

// ---------------- layer-2 edge weights (edge-parallel, latency-tolerant) ----------------
__global__ void wgt2_kernel() {
    int i = blockIdx.x * blockDim.x + threadIdx.x;
    if (i >= E_TOT) return;
    int s = g_csr[i];
    int d = g_dst[i];
    g_w2[i] = __expf(lrelu(g_as2[s] + g_ad2[d]));
}

// ---------------- Aggregation layer 2 + log_softmax (precomputed w2; 4 edges/iter) ----------------
__global__ void __launch_bounds__(256) agg2_kernel(const float* __restrict__ bias2,
                                                   float* __restrict__ out) {
    int gw = (blockIdx.x * blockDim.x + threadIdx.x) >> 5;
    int lane = threadIdx.x & 31;
    if (gw >= N_NODES) return;
    int n = gw;
    int start = g_off[n], end = g_off[n + 1];

    float accLo = 0.f, accHi = 0.f, denom = 0.f;
    int e = start;
    int s[4];
#pragma unroll
    for (int j = 0; j < 4; j++) s[j] = (e + j < end) ? g_csr[e + j] : 0;

    while (e + 3 < end) {
        int ns[4];
#pragma unroll
        for (int j = 0; j < 4; j++) ns[j] = (e + 4 + j < end) ? g_csr[e + 4 + j] : 0;
        float w = (lane < 4) ? g_w2[e + lane] : 0.f;   // 16B coalesced
        denom += w;
#pragma unroll
        for (int j = 0; j < 4; j++) {
            float wj = __shfl_sync(0xffffffffu, w, j);
            if (lane < 20) {
                __half2 h = ((const __half2*)&g_h2p[(size_t)s[j] * 5])[lane];
                float2 f = __half22float2(h);
                accLo += wj * f.x;
                accHi += wj * f.y;
            }
        }
#pragma unroll
        for (int j = 0; j < 4; j++) s[j] = ns[j];
        e += 4;
    }
    int rem = end - e;
    if (rem > 0) {
        float w = (lane < rem) ? g_w2[e + lane] : 0.f;
        denom += w;
        for (int j = 0; j < rem; j++) {
            float wj = __shfl_sync(0xffffffffu, w, j);
            if (lane < 20) {
                __half2 h = ((const __half2*)&g_h2p[(size_t)s[j] * 5])[lane];
                float2 f = __half22float2(h);
                accLo += wj * f.x;
                accHi += wj * f.y;
            }
        }
    }

    denom += __shfl_xor_sync(0xffffffffu, denom, 1);
    denom += __shfl_xor_sync(0xffffffffu, denom, 2);
    float d = __shfl_sync(0xffffffffu, denom, 0) + 1e-16f;

    float r0 = -INFINITY, r1 = -INFINITY;
    if (lane < 20) {
        r0 = accLo / d + bias2[2 * lane];
        r1 = accHi / d + bias2[2 * lane + 1];
    }
    float mm = fmaxf(r0, r1);
#pragma unroll
    for (int o = 16; o > 0; o >>= 1)
        mm = fmaxf(mm, __shfl_xor_sync(0xffffffffu, mm, o));
    float ss = (lane < 20) ? (__expf(r0 - mm) + __expf(r1 - mm)) : 0.f;
#pragma unroll
    for (int o = 16; o > 0; o >>= 1)
        ss += __shfl_xor_sync(0xffffffffu, ss, o);
    float lse = __logf(ss);

    if (lane < 20)
        *(float2*)&out[(size_t)n * C2 + 2 * lane] = make_float2(r0 - mm - lse, r1 - mm - lse);
}

// ---------------- launch ----------------
extern "C" void kernel_launch(void* const* d_in, const int* in_sizes, int n_in,
                              void* d_out, int out_size) {
    const float* x     = (const float*)d_in[0];
    const int*   ei    = (const int*)  d_in[1];
    const float* W1    = (const float*)d_in[2];
    const float* as1   = (const float*)d_in[3];
    const float* ad1   = (const float*)d_in[4];
    const float* b1    = (const float*)d_in[5];
    const float* W2    = (const float*)d_in[6];
    const float* as2   = (const float*)d_in[7];
    const float* ad2   = (const float*)d_in[8];
    const float* b2    = (const float*)d_in[9];
    float* out = (float*)d_out;

    (void)in_sizes; (void)n_in; (void)out_size;

    zero_kernel   <<<(N_NODES + 255) / 256, 256>>>();
    fat1_kernel   <<<G1_BLOCKS + HB_BLOCKS, 256>>>(x, W1, as1, ad1, ei);  // gemm1 || hist
    scanA_kernel  <<<SC_BLOCKS, 256>>>();
    scanB_kernel  <<<1, 512>>>();
    scanC_kernel  <<<SC_BLOCKS, 256>>>();
    scatter_kernel<<<HB_BLOCKS, 256>>>(ei);      // scatter + layer-1 weight precompute

    agg1_kernel   <<<(N_NODES * 32 + 255) / 256, 256>>>(b1);
    gemm2_kernel  <<<(N_NODES + 127) / 128, 128>>>(W2, as2, ad2);
    wgt2_kernel   <<<HB_BLOCKS, 256>>>();
    agg2_kernel   <<<(N_NODES * 32 + 255) / 256, 256>>>(b2, out);
}

// round 13
// speedup vs baseline: 1.2668x; 1.2668x over previous
#include <cuda_runtime.h>
#include <cuda_fp16.h>
#include <math.h>

#define N_NODES 100000
#define E_IN    1600000
#define E_TOT   (E_IN + N_NODES)
#define F_IN    256
#define H1      8
#define C1      64      /* H1*F1 */
#define C2      40      /* classes */

#define G1_BLOCKS ((N_NODES + 127) / 128)          /* 782 gemm1 tiles   */
#define HB_BLOCKS ((E_TOT + 255) / 256)            /* 6641 scatter blks */
#define HIST_BLOCKS 1480                           /* grid-stride hist  */
#define SC_BLOCKS ((N_NODES + 255) / 256)          /* 391 scan blocks   */

// ---------------- scratch (static device globals; no allocation) ----------------
__device__ uint4 g_h1p[(size_t)N_NODES * 8];   // layer-1 features, fp16: 8 halves per uint4
__device__ uint4 g_x2p[(size_t)N_NODES * 8];   // elu output, fp16: 64 halves = 8 uint4
__device__ uint4 g_h2p[(size_t)N_NODES * 5];   // layer-2 features, fp16: 40 halves = 5 uint4
__device__ float g_as1[(size_t)N_NODES * H1];
__device__ float g_ad1[(size_t)N_NODES * H1];
__device__ float g_as2[N_NODES];
__device__ float g_ad2[N_NODES];
__device__ int   g_deg[N_NODES];
__device__ int   g_cur[N_NODES];
__device__ int   g_off[N_NODES + 1];
__device__ int   g_csr[E_TOT];
__device__ int   g_part[SC_BLOCKS];
__device__ int   g_poff[SC_BLOCKS];

// ---------------- helpers ----------------
__device__ __forceinline__ float tf32r(float v) {
    unsigned u;
    asm("cvt.rna.tf32.f32 %0, %1;" : "=r"(u) : "f"(v));
    return __uint_as_float(u);
}
__device__ __forceinline__ void mma_tf32(float* c, const unsigned* a, const unsigned* b) {
    asm volatile(
        "mma.sync.aligned.m16n8k8.row.col.f32.tf32.tf32.f32 "
        "{%0,%1,%2,%3}, {%4,%5,%6,%7}, {%8,%9}, {%0,%1,%2,%3};\n"
        : "+f"(c[0]), "+f"(c[1]), "+f"(c[2]), "+f"(c[3])
        : "r"(a[0]), "r"(a[1]), "r"(a[2]), "r"(a[3]), "r"(b[0]), "r"(b[1]));
}
__device__ __forceinline__ unsigned long long packf2(float a, float b) {
    unsigned long long r;
    asm("mov.b64 %0, {%1, %2};" : "=l"(r) : "f"(a), "f"(b));
    return r;
}
__device__ __forceinline__ void fma2(unsigned long long& d,
                                     unsigned long long a, unsigned long long b) {
    asm("fma.rn.f32x2 %0, %1, %2, %0;" : "+l"(d) : "l"(a), "l"(b));
}
__device__ __forceinline__ float2 unpk(unsigned long long v) {
    float2 r;
    asm("mov.b64 {%0, %1}, %2;" : "=f"(r.x), "=f"(r.y) : "l"(v));
    return r;
}

// ---------------- CSR build ----------------
__global__ void zero_kernel() {
    int i = blockIdx.x * blockDim.x + threadIdx.x;
    if (i < N_NODES) { g_deg[i] = 0; g_cur[i] = 0; }
}

__global__ void scanA_kernel() {
    __shared__ int ws[8];
    int tid = threadIdx.x;
    int i = blockIdx.x * 256 + tid;
    int v = (i < N_NODES) ? g_deg[i] : 0;
    int s = v;
#pragma unroll
    for (int o = 16; o > 0; o >>= 1) s += __shfl_xor_sync(0xffffffffu, s, o);
    if ((tid & 31) == 0) ws[tid >> 5] = s;
    __syncthreads();
    if (tid < 8) {
        int t = ws[tid];
#pragma unroll
        for (int o = 4; o > 0; o >>= 1) t += __shfl_xor_sync(0xffu, t, o);
        if (tid == 0) g_part[blockIdx.x] = t;
    }
}

__global__ void scanB_kernel() {
    __shared__ int sh[512];
    int t = threadIdx.x;
    int v = (t < SC_BLOCKS) ? g_part[t] : 0;
    sh[t] = v;
    __syncthreads();
    for (int o = 1; o < 512; o <<= 1) {
        int u = (t >= o) ? sh[t - o] : 0;
        __syncthreads();
        sh[t] += u;
        __syncthreads();
    }
    if (t < SC_BLOCKS) g_poff[t] = sh[t] - v;    // exclusive
}

__global__ void scanC_kernel() {
    __shared__ int ws[8];
    int tid = threadIdx.x;
    int i = blockIdx.x * 256 + tid;
    int v = (i < N_NODES) ? g_deg[i] : 0;
    int inc = v;
#pragma unroll
    for (int o = 1; o < 32; o <<= 1) {
        int u = __shfl_up_sync(0xffffffffu, inc, o);
        if ((tid & 31) >= o) inc += u;
    }
    if ((tid & 31) == 31) ws[tid >> 5] = inc;
    __syncthreads();
    if (tid < 8) {
        int t = ws[tid];
#pragma unroll
        for (int o = 1; o < 8; o <<= 1) {
            int u = __shfl_up_sync(0xffu, t, o);
            if (tid >= o) t += u;
        }
        ws[tid] = t;
    }
    __syncthreads();
    int wbase = (tid >= 32) ? ws[(tid >> 5) - 1] : 0;
    int excl = g_poff[blockIdx.x] + wbase + inc - v;
    if (i < N_NODES) {
        g_off[i] = excl;
        if (i == N_NODES - 1) g_off[N_NODES] = excl + v;  // == E_TOT
    }
}

__global__ void scatter_kernel(const int* __restrict__ ei) {
    int i = blockIdx.x * blockDim.x + threadIdx.x;
    if (i >= E_TOT) return;
    int d, s;
    if (i < E_IN) { s = ei[i]; d = ei[E_IN + i]; }
    else          { s = i - E_IN; d = i - E_IN; }
    int p = g_off[d] + atomicAdd(&g_cur[d], 1);
    g_csr[p] = s;
}

// ---------------- fat kernel: gemm1 (tf32 mma.sync) || hist (grid-stride) ----------------
__global__ void __launch_bounds__(256) fat1_kernel(
        const float* __restrict__ x, const float* __restrict__ W1,
        const float* __restrict__ a_s, const float* __restrict__ a_d,
        const int* __restrict__ ei) {
    __shared__ __align__(16) float smem_pool[128 * 65];
    int tid = threadIdx.x;

    if (blockIdx.x >= G1_BLOCKS) {
        // ---- hist path: grid-stride over all edges ----
        for (int i = (blockIdx.x - G1_BLOCKS) * 256 + tid; i < E_TOT;
             i += HIST_BLOCKS * 256) {
            int d = (i < E_IN) ? ei[E_IN + i] : (i - E_IN);
            atomicAdd(&g_deg[d], 1);
        }
        return;
    }

    float (*Xs)[33] = (float (*)[33])smem_pool;
    float (*Ws)[64] = (float (*)[64])(smem_pool + 128 * 33);
    float (*Cs)[65] = (float (*)[65])smem_pool;

    int lane = tid & 31;
    int warp = tid >> 5;
    int rg = warp >> 1;
    int cg = warp & 1;
    int row0 = blockIdx.x * 128;

    float acc[2][4][4];
#pragma unroll
    for (int m = 0; m < 2; m++)
#pragma unroll
        for (int j = 0; j < 4; j++)
#pragma unroll
            for (int q = 0; q < 4; q++) acc[m][j][q] = 0.f;

    float4 xbuf[4];
    float4 wbuf[2];
#pragma unroll
    for (int i = 0; i < 4; i++) {
        int idx = tid + i * 256; int r = idx >> 3, q = idx & 7;
        int gr = row0 + r;
        xbuf[i] = (gr < N_NODES) ? *(const float4*)&x[(size_t)gr * F_IN + q * 4]
                                 : make_float4(0.f, 0.f, 0.f, 0.f);
    }
#pragma unroll
    for (int i = 0; i < 2; i++) {
        int idx = tid + i * 256; int r = idx >> 4, q = idx & 15;
        wbuf[i] = *(const float4*)&W1[(size_t)r * C1 + q * 4];
    }

    for (int kt = 0; kt < F_IN; kt += 32) {
#pragma unroll
        for (int i = 0; i < 4; i++) {
            int idx = tid + i * 256; int r = idx >> 3, q = idx & 7;
            Xs[r][q * 4 + 0] = tf32r(xbuf[i].x); Xs[r][q * 4 + 1] = tf32r(xbuf[i].y);
            Xs[r][q * 4 + 2] = tf32r(xbuf[i].z); Xs[r][q * 4 + 3] = tf32r(xbuf[i].w);
        }
#pragma unroll
        for (int i = 0; i < 2; i++) {
            int idx = tid + i * 256; int r = idx >> 4, q = idx & 15;
            Ws[r][q * 4 + 0] = tf32r(wbuf[i].x); Ws[r][q * 4 + 1] = tf32r(wbuf[i].y);
            Ws[r][q * 4 + 2] = tf32r(wbuf[i].z); Ws[r][q * 4 + 3] = tf32r(wbuf[i].w);
        }
        __syncthreads();

        int ktn = kt + 32;
        if (ktn < F_IN) {
#pragma unroll
            for (int i = 0; i < 4; i++) {
                int idx = tid + i * 256; int r = idx >> 3, q = idx & 7;
                int gr = row0 + r;
                xbuf[i] = (gr < N_NODES) ? *(const float4*)&x[(size_t)gr * F_IN + ktn + q * 4]
                                         : make_float4(0.f, 0.f, 0.f, 0.f);
            }
#pragma unroll
            for (int i = 0; i < 2; i++) {
                int idx = tid + i * 256; int r = idx >> 4, q = idx & 15;
                wbuf[i] = *(const float4*)&W1[(size_t)(ktn + r) * C1 + q * 4];
            }
        }

#pragma unroll
        for (int ks = 0; ks < 4; ks++) {
            int k0 = ks * 8;
            unsigned afr[2][4];
#pragma unroll
            for (int m = 0; m < 2; m++) {
                int R = rg * 32 + m * 16;
                afr[m][0] = __float_as_uint(Xs[R + (lane >> 2)][k0 + (lane & 3)]);
                afr[m][1] = __float_as_uint(Xs[R + (lane >> 2) + 8][k0 + (lane & 3)]);
                afr[m][2] = __float_as_uint(Xs[R + (lane >> 2)][k0 + (lane & 3) + 4]);
                afr[m][3] = __float_as_uint(Xs[R + (lane >> 2) + 8][k0 + (lane & 3) + 4]);
            }
            unsigned bfr[4][2];
#pragma unroll
            for (int j = 0; j < 4; j++) {
                int Cb = cg * 32 + j * 8;
                bfr[j][0] = __float_as_uint(Ws[k0 + (lane & 3)][Cb + (lane >> 2)]);
                bfr[j][1] = __float_as_uint(Ws[k0 + (lane & 3) + 4][Cb + (lane >> 2)]);
            }
#pragma unroll
            for (int m = 0; m < 2; m++)
#pragma unroll
                for (int j = 0; j < 4; j++)
                    mma_tf32(acc[m][j], afr[m], bfr[j]);
        }
        __syncthreads();
    }

#pragma unroll
    for (int m = 0; m < 2; m++) {
        int R = rg * 32 + m * 16 + (lane >> 2);
#pragma unroll
        for (int j = 0; j < 4; j++) {
            int Cb = cg * 32 + j * 8 + 2 * (lane & 3);
            Cs[R][Cb]         = acc[m][j][0];
            Cs[R][Cb + 1]     = acc[m][j][1];
            Cs[R + 8][Cb]     = acc[m][j][2];
            Cs[R + 8][Cb + 1] = acc[m][j][3];
        }
    }
    __syncthreads();

    {
        int r = tid >> 1;
        int half = tid & 1;
        int gr = row0 + r;
        if (gr < N_NODES) {
            int c0 = half * 32;
            float f[32];
#pragma unroll
            for (int q = 0; q < 32; q++) f[q] = Cs[r][c0 + q];
#pragma unroll
            for (int h = 0; h < 4; h++) {
                int head = half * 4 + h;
                float ps = 0.f, pd = 0.f;
#pragma unroll
                for (int q = 0; q < 8; q++) {
                    ps += f[h * 8 + q] * a_s[head * 8 + q];
                    pd += f[h * 8 + q] * a_d[head * 8 + q];
                }
                g_as1[gr * H1 + head] = ps;
                g_ad1[gr * H1 + head] = pd;
            }
#pragma unroll
            for (int u = 0; u < 4; u++) {
                __half2 hh[4];
#pragma unroll
                for (int q = 0; q < 4; q++)
                    hh[q] = __floats2half2_rn(f[u * 8 + 2 * q], f[u * 8 + 2 * q + 1]);
                g_h1p[(size_t)gr * 8 + half * 4 + u] = *(uint4*)hh;
            }
        }
    }
}

// ---------------- Aggregation layer 1 (warp per dst; fp16 gather; 4 edges/iter) ----------------
// Lane owns half2 #lane (features 2*lane, 2*lane+1) -> head hA = lane>>2.
// Weight duty: lane computes w for edge slot (lane>>3), head (lane&7).
__global__ void __launch_bounds__(256) agg1_kernel(const float* __restrict__ bias1) {
    int gw = (blockIdx.x * blockDim.x + threadIdx.x) >> 5;
    int lane = threadIdx.x & 31;
    if (gw >= N_NODES) return;
    int n = gw;
    int start = g_off[n], end = g_off[n + 1];

    int head = lane & 7;
    int slot = lane >> 3;
    int hA = lane >> 2;
    float adv = g_ad1[n * H1 + head];

    float accLo = 0.f, accHi = 0.f, denom = 0.f;
    int e = start;
    int s[4];
#pragma unroll
    for (int j = 0; j < 4; j++) s[j] = (e + j < end) ? g_csr[e + j] : 0;

    while (e + 3 < end) {
        int ns[4];
#pragma unroll
        for (int j = 0; j < 4; j++) ns[j] = (e + 4 + j < end) ? g_csr[e + 4 + j] : 0;
        float v = g_as1[s[slot] * H1 + head] + adv;
        v = v > 0.f ? v : 0.2f * v;
        float w = __expf(v);
        denom += w;
#pragma unroll
        for (int j = 0; j < 4; j++) {
            float wj = __shfl_sync(0xffffffffu, w, j * 8 + hA);
            __half2 h = ((const __half2*)&g_h1p[(size_t)s[j] * 8])[lane];
            float2 f = __half22float2(h);
            accLo += wj * f.x;
            accHi += wj * f.y;
        }
#pragma unroll
        for (int j = 0; j < 4; j++) s[j] = ns[j];
        e += 4;
    }
    int rem = end - e;           // 0..3, uniform per warp
    if (rem > 0) {
        float w = 0.f;
        if (slot < rem) {
            float v = g_as1[s[slot] * H1 + head] + adv;
            v = v > 0.f ? v : 0.2f * v;
            w = __expf(v);
            denom += w;
        }
        for (int j = 0; j < rem; j++) {
            float wj = __shfl_sync(0xffffffffu, w, j * 8 + hA);
            __half2 h = ((const __half2*)&g_h1p[(size_t)s[j] * 8])[lane];
            float2 f = __half22float2(h);
            accLo += wj * f.x;
            accHi += wj * f.y;
        }
    }

    denom += __shfl_xor_sync(0xffffffffu, denom, 8);
    denom += __shfl_xor_sync(0xffffffffu, denom, 16);
    float dA = __shfl_sync(0xffffffffu, denom, hA) + 1e-16f;
    float oLo = accLo / dA + bias1[2 * lane];
    float oHi = accHi / dA + bias1[2 * lane + 1];
    oLo = oLo > 0.f ? oLo : expm1f(oLo);
    oHi = oHi > 0.f ? oHi : expm1f(oHi);
    // packed fp16 x2: warp writes one coalesced 128B row
    ((__half2*)&g_x2p[(size_t)n * 8])[lane] = __floats2half2_rn(oLo, oHi);
}

// ---------------- GEMM2: thread-per-node (fp16 in), fp16 packed output ----------------
__global__ void __launch_bounds__(128) gemm2_kernel(
        const float* __restrict__ W2,
        const float* __restrict__ a_s2, const float* __restrict__ a_d2) {
    __shared__ float Ws[C1][C2];
    __shared__ float Xs[128][65];
    int tid = threadIdx.x;
    int n0 = blockIdx.x * 128;
    int gn = n0 + tid;

    for (int i = tid; i < C1 * C2; i += 128) ((float*)Ws)[i] = W2[i];
    // fill Xs from packed fp16 x2: 128 rows x 8 uint4
#pragma unroll
    for (int i = 0; i < 8; i++) {
        int idx = tid + i * 128; int r = idx >> 3, q = idx & 7;
        int gr = n0 + r;
        uint4 v = (gr < N_NODES) ? g_x2p[(size_t)gr * 8 + q]
                                 : make_uint4(0u, 0u, 0u, 0u);
        const __half2* hp = (const __half2*)&v;
#pragma unroll
        for (int t = 0; t < 4; t++) {
            float2 f = __half22float2(hp[t]);
            Xs[r][q * 8 + 2 * t]     = f.x;
            Xs[r][q * 8 + 2 * t + 1] = f.y;
        }
    }
    __syncthreads();

    unsigned long long acc2[20];
#pragma unroll
    for (int j = 0; j < 20; j++) acc2[j] = 0ull;

    if (gn < N_NODES) {
#pragma unroll 4
        for (int k = 0; k < C1; k++) {
            float a = Xs[tid][k];
            unsigned long long ap = packf2(a, a);
            const unsigned long long* wp = (const unsigned long long*)&Ws[k][0];
#pragma unroll
            for (int j = 0; j < 20; j++) fma2(acc2[j], ap, wp[j]);
        }
        float ps = 0.f, pd = 0.f;
        __half2 hh[20];
#pragma unroll
        for (int j = 0; j < 20; j++) {
            float2 p = unpk(acc2[j]);
            hh[j] = __floats2half2_rn(p.x, p.y);
            ps += p.x * a_s2[2 * j] + p.y * a_s2[2 * j + 1];
            pd += p.x * a_d2[2 * j] + p.y * a_d2[2 * j + 1];
        }
        const uint4* hv = (const uint4*)hh;
#pragma unroll
        for (int u = 0; u < 5; u++) g_h2p[(size_t)gn * 5 + u] = hv[u];
        g_as2[gn] = ps;
        g_ad2[gn] = pd;
    }
}

// ---------------- Aggregation layer 2 + log_softmax (fp16 rows; 4 edges/iter) ----------------
// Lanes 0-19 own half2 #lane = classes (2*lane, 2*lane+1). Lanes 0-3 compute weights.
__global__ void __launch_bounds__(256) agg2_kernel(const float* __restrict__ bias2,
                                                   float* __restrict__ out) {
    int gw = (blockIdx.x * blockDim.x + threadIdx.x) >> 5;
    int lane = threadIdx.x & 31;
    if (gw >= N_NODES) return;
    int n = gw;
    int start = g_off[n], end = g_off[n + 1];
    float adv = g_ad2[n];

    float accLo = 0.f, accHi = 0.f, denom = 0.f;
    int e = start;
    int s[4];
#pragma unroll
    for (int j = 0; j < 4; j++) s[j] = (e + j < end) ? g_csr[e + j] : 0;

    while (e + 3 < end) {
        int ns[4];
#pragma unroll
        for (int j = 0; j < 4; j++) ns[j] = (e + 4 + j < end) ? g_csr[e + 4 + j] : 0;
        float w = 0.f;
        if (lane < 4) {
            float v = g_as2[s[lane]] + adv;
            v = v > 0.f ? v : 0.2f * v;
            w = __expf(v);
            denom += w;
        }
#pragma unroll
        for (int j = 0; j < 4; j++) {
            float wj = __shfl_sync(0xffffffffu, w, j);
            if (lane < 20) {
                __half2 h = ((const __half2*)&g_h2p[(size_t)s[j] * 5])[lane];
                float2 f = __half22float2(h);
                accLo += wj * f.x;
                accHi += wj * f.y;
            }
        }
#pragma unroll
        for (int j = 0; j < 4; j++) s[j] = ns[j];
        e += 4;
    }
    int rem = end - e;
    if (rem > 0) {
        float w = 0.f;
        if (lane < rem) {
            float v = g_as2[s[lane]] + adv;
            v = v > 0.f ? v : 0.2f * v;
            w = __expf(v);
            denom += w;
        }
        for (int j = 0; j < rem; j++) {
            float wj = __shfl_sync(0xffffffffu, w, j);
            if (lane < 20) {
                __half2 h = ((const __half2*)&g_h2p[(size_t)s[j] * 5])[lane];
                float2 f = __half22float2(h);
                accLo += wj * f.x;
                accHi += wj * f.y;
            }
        }
    }

    denom += __shfl_xor_sync(0xffffffffu, denom, 1);
    denom += __shfl_xor_sync(0xffffffffu, denom, 2);
    float d = __shfl_sync(0xffffffffu, denom, 0) + 1e-16f;

    float r0 = -INFINITY, r1 = -INFINITY;
    if (lane < 20) {
        r0 = accLo / d + bias2[2 * lane];
        r1 = accHi / d + bias2[2 * lane + 1];
    }
    float mm = fmaxf(r0, r1);
#pragma unroll
    for (int o = 16; o > 0; o >>= 1)
        mm = fmaxf(mm, __shfl_xor_sync(0xffffffffu, mm, o));
    float ss = (lane < 20) ? (__expf(r0 - mm) + __expf(r1 - mm)) : 0.f;
#pragma unroll
    for (int o = 16; o > 0; o >>= 1)
        ss += __shfl_xor_sync(0xffffffffu, ss, o);
    float lse = __logf(ss);

    if (lane < 20)
        *(float2*)&out[(size_t)n * C2 + 2 * lane] = make_float2(r0 - mm - lse, r1 - mm - lse);
}

// ---------------- launch ----------------
extern "C" void kernel_launch(void* const* d_in, const int* in_sizes, int n_in,
                              void* d_out, int out_size) {
    const float* x     = (const float*)d_in[0];
    const int*   ei    = (const int*)  d_in[1];
    const float* W1    = (const float*)d_in[2];
    const float* as1   = (const float*)d_in[3];
    const float* ad1   = (const float*)d_in[4];
    const float* b1    = (const float*)d_in[5];
    const float* W2    = (const float*)d_in[6];
    const float* as2   = (const float*)d_in[7];
    const float* ad2   = (const float*)d_in[8];
    const float* b2    = (const float*)d_in[9];
    float* out = (float*)d_out;

    (void)in_sizes; (void)n_in; (void)out_size;

    zero_kernel   <<<(N_NODES + 255) / 256, 256>>>();
    fat1_kernel   <<<G1_BLOCKS + HIST_BLOCKS, 256>>>(x, W1, as1, ad1, ei); // gemm1 || hist
    scanA_kernel  <<<SC_BLOCKS, 256>>>();
    scanB_kernel  <<<1, 512>>>();
    scanC_kernel  <<<SC_BLOCKS, 256>>>();
    scatter_kernel<<<HB_BLOCKS, 256>>>(ei);

    agg1_kernel   <<<(N_NODES * 32 + 255) / 256, 256>>>(b1);
    gemm2_kernel  <<<(N_NODES + 127) / 128, 128>>>(W2, as2, ad2);
    agg2_kernel   <<<(N_NODES * 32 + 255) / 256, 256>>>(b2, out);
}